// round 1
// baseline (speedup 1.0000x reference)
#include <cuda_runtime.h>
#include <math.h>
#include <stdint.h>

// ---------------- problem constants ----------------
#define MAXB     1024
#define DIM      128
#define NCHUNKS  18
#define QT       128          // queries per CTA tile
#define KT       128          // keys per inner tile
#define ROWS     132          // padded smem row stride (floats); 132%32=4 -> low conflicts
#define TOPK     5
#define INV_T    10.0f        // 1/temperature

// ---------------- device scratch (no allocations allowed) ----------------
__device__ float g_qn[MAXB * DIM];                       // normalized queries
__device__ int   g_excl[MAXB];                           // decoded exclude indices
__device__ float g_pval[8 * NCHUNKS * 128 * TOPK];       // partial top-5 values
__device__ int   g_pidx[8 * NCHUNKS * 128 * TOPK];       // partial top-5 indices

// ---------------- helpers ----------------
__device__ __forceinline__ void fma2(unsigned long long &d,
                                     unsigned long long a,
                                     unsigned long long b) {
    // packed f32x2 FMA: d.lo += a.lo*b.lo ; d.hi += a.hi*b.hi
    asm("fma.rn.f32x2 %0, %1, %2, %0;" : "+l"(d) : "l"(a), "l"(b));
}

__device__ __forceinline__ float pairsum(unsigned long long u) {
    float lo = __uint_as_float((unsigned)(u & 0xffffffffULL));
    float hi = __uint_as_float((unsigned)(u >> 32));
    return lo + hi;
}

__device__ __forceinline__ void cp16(void* s, const void* g) {
    unsigned sa = (unsigned)__cvta_generic_to_shared(s);
    asm volatile("cp.async.cg.shared.global [%0], [%1], 16;" :: "r"(sa), "l"(g));
}
__device__ __forceinline__ void cp_commit() {
    asm volatile("cp.async.commit_group;");
}

// ---------------- kernel 1: normalize queries ----------------
__global__ void prep_q(const float* __restrict__ q, int B) {
    int w    = (blockIdx.x * blockDim.x + threadIdx.x) >> 5;   // one warp per query
    int lane = threadIdx.x & 31;
    if (w >= B) return;
    float4 v = *(const float4*)(q + (size_t)w * DIM + lane * 4);
    float ss = v.x * v.x + v.y * v.y + v.z * v.z + v.w * v.w;
    #pragma unroll
    for (int o = 16; o; o >>= 1) ss += __shfl_xor_sync(0xffffffffu, ss, o);
    float sc = 1.0f / fmaxf(sqrtf(ss), 1e-12f);
    float4 r = make_float4(v.x * sc, v.y * sc, v.z * sc, v.w * sc);
    *(float4*)(g_qn + (size_t)w * DIM + lane * 4) = r;
}

// ---------------- kernel 2: decode exclude indices (int32 vs int64 sniff) ---
__global__ void decode_exclude(const void* __restrict__ ex, int B) {
    __shared__ int nz;
    int t = threadIdx.x;
    if (t == 0) nz = 0;
    __syncthreads();
    const int* e32 = (const int*)ex;
    // int64 data => odd int32 words (high halves, values < 2^31) are all zero.
    if (t < B / 2) { if (e32[2 * t + 1] != 0) atomicAdd(&nz, 1); }
    __syncthreads();
    bool is64 = (nz == 0);
    if (t < B) {
        long long v = is64 ? ((const long long*)ex)[t] : (long long)e32[t];
        g_excl[t] = (int)v;
    }
}

// ---------------- kernel 3: fused sim GEMM + streaming top-5 ----------------
__device__ __forceinline__ void load_tile(float* buf, const float* __restrict__ mem,
                                          int key0, int N, int tid) {
    #pragma unroll 4
    for (int c = tid; c < KT * 32; c += 256) {
        int r   = c >> 5;
        int col = (c & 31) * 4;
        float* dst = buf + r * ROWS + col;
        int key = key0 + r;
        if (key < N) cp16(dst, mem + (size_t)key * DIM + col);
        else         *(float4*)dst = make_float4(0.f, 0.f, 0.f, 0.f);
    }
    cp_commit();
}

__global__ void __launch_bounds__(256, 1)
sim_topk(const float* __restrict__ mem, int N) {
    extern __shared__ float sm[];
    float* qs  = sm;                                 // [QT][ROWS]
    float* ks0 = sm + QT * ROWS;                     // [KT][ROWS]
    float* ks1 = ks0 + KT * ROWS;

    int tid   = threadIdx.x;
    int qtile = blockIdx.x;
    int chunk = blockIdx.y;
    int qbase = qtile * 128;

    // stage the (pre-normalized) query tile once
    #pragma unroll 4
    for (int idx = tid; idx < QT * 32; idx += 256) {
        int q = idx >> 5, c = (idx & 31) * 4;
        *(float4*)(qs + q * ROWS + c) = *(const float4*)(g_qn + (size_t)(qbase + q) * DIM + c);
    }

    int Ntiles = (N + 127) >> 7;
    int TPC    = (Ntiles + NCHUNKS - 1) / NCHUNKS;
    int t0     = chunk * TPC;
    int t1     = min(t0 + TPC, Ntiles);
    int T      = t1 - t0;

    float tv[TOPK]; int ti[TOPK];
    #pragma unroll
    for (int r = 0; r < TOPK; ++r) { tv[r] = -INFINITY; ti[r] = -1; }
    int exq = (tid < 128) ? g_excl[qbase + tid] : -2;

    if (T > 0) load_tile(ks0, mem, t0 * 128, N, tid);

    int ty = tid >> 4, tx = tid & 15;

    for (int t = 0; t < T; ++t) {
        float* cur = (t & 1) ? ks1 : ks0;
        if (t + 1 < T) {
            load_tile((t & 1) ? ks0 : ks1, mem, (t0 + t + 1) * 128, N, tid);
            asm volatile("cp.async.wait_group 1;");
        } else {
            asm volatile("cp.async.wait_group 0;");
        }
        __syncthreads();

        // ---- 128x128 sim tile, 8x8 per-thread register block, packed f32x2 FMAs
        unsigned long long acc[8][8];
        #pragma unroll
        for (int i = 0; i < 8; ++i)
            #pragma unroll
            for (int j = 0; j < 8; ++j) acc[i][j] = 0ULL;

        const float* qp = qs + (ty * 8) * ROWS;
        const float* kp = cur + tx * ROWS;

        #pragma unroll 1
        for (int kk = 0; kk < DIM; kk += 4) {
            ulonglong2 qv[8], mv[8];
            #pragma unroll
            for (int i = 0; i < 8; ++i)
                qv[i] = *(const ulonglong2*)(qp + i * ROWS + kk);
            #pragma unroll
            for (int j = 0; j < 8; ++j)
                mv[j] = *(const ulonglong2*)(kp + (16 * j) * ROWS + kk);
            #pragma unroll
            for (int i = 0; i < 8; ++i)
                #pragma unroll
                for (int j = 0; j < 8; ++j) {
                    fma2(acc[i][j], qv[i].x, mv[j].x);
                    fma2(acc[i][j], qv[i].y, mv[j].y);
                }
        }
        __syncthreads();   // everyone done reading cur

        // spill sims into the consumed buffer: sim[q_local][k_local]
        #pragma unroll
        for (int i = 0; i < 8; ++i)
            #pragma unroll
            for (int j = 0; j < 8; ++j)
                cur[(ty * 8 + i) * ROWS + tx + 16 * j] = pairsum(acc[i][j]);
        __syncthreads();

        // ---- streaming top-5 scan: one thread per query row
        if (tid < 128) {
            const float* row = cur + tid * ROWS;
            int key0 = (t0 + t) * 128;
            #pragma unroll 4
            for (int k = 0; k < 128; k += 4) {
                float4 s4 = *(const float4*)(row + k);
                float sv[4] = { s4.x, s4.y, s4.z, s4.w };
                #pragma unroll
                for (int u = 0; u < 4; ++u) {
                    float s = sv[u];
                    int kg = key0 + k + u;
                    if (s > tv[TOPK - 1] && kg < N && kg != exq) {
                        tv[4] = s; ti[4] = kg;
                        #pragma unroll
                        for (int p = 4; p > 0; --p) {
                            if (tv[p] > tv[p - 1]) {
                                float fv = tv[p]; tv[p] = tv[p - 1]; tv[p - 1] = fv;
                                int fi = ti[p]; ti[p] = ti[p - 1]; ti[p - 1] = fi;
                            }
                        }
                    }
                }
            }
        }
        __syncthreads();   // scan done before next iteration overwrites buffers
    }

    if (tid < 128) {
        size_t base = ((size_t)(qtile * NCHUNKS + chunk) * 128 + tid) * TOPK;
        #pragma unroll
        for (int r = 0; r < TOPK; ++r) { g_pval[base + r] = tv[r]; g_pidx[base + r] = ti[r]; }
    }
}

// ---------------- kernel 4: merge partials, softmax, gather, normalize ------
__global__ void merge_out(const float* __restrict__ mem, float* __restrict__ out,
                          int N, int B) {
    int q    = (blockIdx.x * blockDim.x + threadIdx.x) >> 5;   // one warp per query
    int lane = threadIdx.x & 31;
    if (q >= B) return;
    int qtile = q >> 7, ql = q & 127;

    const int NCAND = NCHUNKS * TOPK;   // 90
    float cv[3]; int ci[3];
    #pragma unroll
    for (int s = 0; s < 3; ++s) {
        int cidx = lane + 32 * s;
        if (cidx < NCAND) {
            int c = cidx / TOPK, r = cidx % TOPK;
            size_t base = ((size_t)(qtile * NCHUNKS + c) * 128 + ql) * TOPK + r;
            cv[s] = g_pval[base]; ci[s] = g_pidx[base];
        } else { cv[s] = -INFINITY; ci[s] = 0x7fffffff; }
    }

    float tv[TOPK]; int ti[TOPK];
    #pragma unroll
    for (int r5 = 0; r5 < TOPK; ++r5) {
        float bv = cv[0]; int bi = ci[0];
        #pragma unroll
        for (int s = 1; s < 3; ++s)
            if (cv[s] > bv || (cv[s] == bv && ci[s] < bi)) { bv = cv[s]; bi = ci[s]; }
        float rv = bv; int ri = bi;
        #pragma unroll
        for (int o = 16; o; o >>= 1) {
            float ov = __shfl_xor_sync(0xffffffffu, rv, o);
            int   oi = __shfl_xor_sync(0xffffffffu, ri, o);
            if (ov > rv || (ov == rv && oi < ri)) { rv = ov; ri = oi; }
        }
        tv[r5] = rv; ti[r5] = ri;
        #pragma unroll
        for (int s = 0; s < 3; ++s) if (ci[s] == ri) cv[s] = -INFINITY;
    }

    // softmax over top_sim / T  (tv[0] is the max)
    float e[TOPK], ssum = 0.f;
    #pragma unroll
    for (int k = 0; k < TOPK; ++k) { e[k] = expf((tv[k] - tv[0]) * INV_T); ssum += e[k]; }
    float w[TOPK];
    #pragma unroll
    for (int k = 0; k < TOPK; ++k) w[k] = e[k] / ssum;

    // weighted gather of memory rows + renormalize
    int d0 = lane * 4;
    float4 a = make_float4(0.f, 0.f, 0.f, 0.f);
    #pragma unroll
    for (int k = 0; k < TOPK; ++k) {
        float4 m4 = *(const float4*)(mem + (size_t)ti[k] * DIM + d0);
        a.x += w[k] * m4.x; a.y += w[k] * m4.y; a.z += w[k] * m4.z; a.w += w[k] * m4.w;
    }
    float ss = a.x * a.x + a.y * a.y + a.z * a.z + a.w * a.w;
    #pragma unroll
    for (int o = 16; o; o >>= 1) ss += __shfl_xor_sync(0xffffffffu, ss, o);
    float sc = 1.0f / fmaxf(sqrtf(ss), 1e-12f);
    float4 r4 = make_float4(a.x * sc, a.y * sc, a.z * sc, a.w * sc);
    *(float4*)(out + (size_t)q * DIM + d0) = r4;

    if (lane == 0) {
        out[(size_t)B * DIM + q] = 1.0f - tv[0];                 // distances
        #pragma unroll
        for (int k = 0; k < TOPK; ++k)
            out[(size_t)B * DIM + B + (size_t)q * TOPK + k] = w[k];  // weights
    }
}

// ---------------- launch ----------------
extern "C" void kernel_launch(void* const* d_in, const int* in_sizes, int n_in,
                              void* d_out, int out_size) {
    const float* query  = (const float*)d_in[0];
    const float* memory = (const float*)d_in[1];
    const void*  excl   = d_in[3];
    int B = in_sizes[0] / DIM;      // 1024
    int N = in_sizes[1] / DIM;      // 200000
    float* out = (float*)d_out;

    prep_q<<<(B * 32 + 255) / 256, 256>>>(query, B);
    decode_exclude<<<1, 1024>>>(excl, B);

    const int SMEM = (QT + 2 * KT) * ROWS * (int)sizeof(float);  // 202752 B
    cudaFuncSetAttribute(sim_topk, cudaFuncAttributeMaxDynamicSharedMemorySize, SMEM);
    sim_topk<<<dim3(B / 128, NCHUNKS), 256, SMEM>>>(memory, N);

    merge_out<<<(B * 32 + 255) / 256, 256>>>(memory, out, N, B);
}

// round 3
// speedup vs baseline: 2.3839x; 2.3839x over previous
#include <cuda_runtime.h>
#include <cuda_bf16.h>
#include <math.h>
#include <stdint.h>

// ---------------- problem constants ----------------
#define MAXB     1024
#define DIM      128
#define NCHUNKS  18
#define TOPK     5
#define INV_T    10.0f
#define NPADMAX  (1564 * 128)

// ---------------- device scratch ----------------
__device__ int   g_excl[MAXB];
__device__ float g_pval[8 * NCHUNKS * 128 * TOPK];
__device__ int   g_pidx[8 * NCHUNKS * 128 * TOPK];
__device__ __nv_bfloat16 g_qh[MAXB * DIM];
__device__ __nv_bfloat16 g_ql[MAXB * DIM];
__device__ __nv_bfloat16 g_kh[(size_t)NPADMAX * DIM];   // 51.2 MB
__device__ __nv_bfloat16 g_kl[(size_t)NPADMAX * DIM];   // 51.2 MB

// ---------------- PTX helpers ----------------
__device__ __forceinline__ uint32_t smem_u32(const void* p) {
    uint32_t a;
    asm("{ .reg .u64 t; cvta.to.shared.u64 t, %1; cvt.u32.u64 %0, t; }" : "=r"(a) : "l"(p));
    return a;
}
__device__ __forceinline__ void cp16(uint32_t s, const void* g) {
    asm volatile("cp.async.cg.shared.global [%0], [%1], 16;" :: "r"(s), "l"(g));
}
#define CP_COMMIT()  asm volatile("cp.async.commit_group;")
#define CP_WAIT(n)   asm volatile("cp.async.wait_group %0;" :: "n"(n))

#define LDSM4(r0, r1, r2, r3, addr)                                         \
    asm volatile("ldmatrix.sync.aligned.m8n8.x4.shared.b16 {%0,%1,%2,%3}, [%4];" \
                 : "=r"(r0), "=r"(r1), "=r"(r2), "=r"(r3) : "r"(addr))

#define MMA16816(c, a, b0, b1)                                              \
    asm volatile("mma.sync.aligned.m16n8k16.row.col.f32.bf16.bf16.f32 "     \
                 "{%0,%1,%2,%3},{%4,%5,%6,%7},{%8,%9},{%0,%1,%2,%3};"       \
                 : "+f"((c)[0]), "+f"((c)[1]), "+f"((c)[2]), "+f"((c)[3])   \
                 : "r"((a)[0]), "r"((a)[1]), "r"((a)[2]), "r"((a)[3]),      \
                   "r"(b0), "r"(b1))

// ---------------- top-5 helpers (register resident) ----------------
__device__ __forceinline__ void t5_ins(float (&tv)[5], int (&ti)[5], float s, int idx) {
    tv[4] = s; ti[4] = idx;
    #pragma unroll
    for (int p = 4; p > 0; --p) {
        if (tv[p] > tv[p - 1]) {
            float fv = tv[p]; tv[p] = tv[p - 1]; tv[p - 1] = fv;
            int fi = ti[p]; ti[p] = ti[p - 1]; ti[p - 1] = fi;
        }
    }
}
__device__ __forceinline__ void t5_merge_xor(float (&tv)[5], int (&ti)[5], int off) {
    float pv[5]; int pi[5];
    #pragma unroll
    for (int r = 0; r < 5; ++r) {
        pv[r] = __shfl_xor_sync(0xffffffffu, tv[r], off);
        pi[r] = __shfl_xor_sync(0xffffffffu, ti[r], off);
    }
    #pragma unroll
    for (int r = 0; r < 5; ++r)
        if (pv[r] > tv[4]) t5_ins(tv, ti, pv[r], pi[r]);
}

// ---------------- kernel: normalize queries + bf16 hi/lo split --------------
__global__ void prep_q(const float* __restrict__ q, int B) {
    int w = (blockIdx.x * blockDim.x + threadIdx.x) >> 5;
    int lane = threadIdx.x & 31;
    if (w >= B) return;
    float4 v = *(const float4*)(q + (size_t)w * DIM + lane * 4);
    float ss = v.x * v.x + v.y * v.y + v.z * v.z + v.w * v.w;
    #pragma unroll
    for (int o = 16; o; o >>= 1) ss += __shfl_xor_sync(0xffffffffu, ss, o);
    float sc = 1.0f / fmaxf(sqrtf(ss), 1e-12f);
    float e[4] = { v.x * sc, v.y * sc, v.z * sc, v.w * sc };
    __nv_bfloat162 h0 = __floats2bfloat162_rn(e[0], e[1]);
    __nv_bfloat162 h1 = __floats2bfloat162_rn(e[2], e[3]);
    __nv_bfloat162 l0 = __floats2bfloat162_rn(e[0] - __low2float(h0), e[1] - __high2float(h0));
    __nv_bfloat162 l1 = __floats2bfloat162_rn(e[2] - __low2float(h1), e[3] - __high2float(h1));
    size_t off = (size_t)w * DIM + lane * 4;
    *(uint2*)(g_qh + off) = make_uint2(*(uint32_t*)&h0, *(uint32_t*)&h1);
    *(uint2*)(g_ql + off) = make_uint2(*(uint32_t*)&l0, *(uint32_t*)&l1);
}

// ---------------- kernel: decode exclude (int32/int64 sniff) ----------------
__global__ void decode_exclude(const void* __restrict__ ex, int B) {
    __shared__ int nz;
    int t = threadIdx.x;
    if (t == 0) nz = 0;
    __syncthreads();
    const int* e32 = (const int*)ex;
    if (t < B / 2) { if (e32[2 * t + 1] != 0) atomicAdd(&nz, 1); }
    __syncthreads();
    bool is64 = (nz == 0);
    if (t < B) {
        long long v = is64 ? ((const long long*)ex)[t] : (long long)e32[t];
        g_excl[t] = (int)v;
    }
}

// ---------------- kernel: fp32 memory -> bf16 hi/lo split ----------------
__global__ void split_mem(const float* __restrict__ mem, int N, int NPAD) {
    int total4 = NPAD * (DIM / 4);
    for (int i = blockIdx.x * blockDim.x + threadIdx.x; i < total4;
         i += gridDim.x * blockDim.x) {
        int row = i >> 5;
        float4 v = make_float4(0.f, 0.f, 0.f, 0.f);
        if (row < N) v = ((const float4*)mem)[i];
        __nv_bfloat162 h0 = __floats2bfloat162_rn(v.x, v.y);
        __nv_bfloat162 h1 = __floats2bfloat162_rn(v.z, v.w);
        __nv_bfloat162 l0 = __floats2bfloat162_rn(v.x - __low2float(h0), v.y - __high2float(h0));
        __nv_bfloat162 l1 = __floats2bfloat162_rn(v.z - __low2float(h1), v.w - __high2float(h1));
        ((uint2*)g_kh)[i] = make_uint2(*(uint32_t*)&h0, *(uint32_t*)&h1);
        ((uint2*)g_kl)[i] = make_uint2(*(uint32_t*)&l0, *(uint32_t*)&l1);
    }
}

// ---------------- key tile loader (XOR-swizzled rows for ldmatrix) ----------
// stage layout: [kh: 128 rows x 256B][kl: same]. row r, 16B chunk c (0..15):
// off = r*256 + ((c ^ (r&7)) << 4)
__device__ __forceinline__ void load_ktile(uint32_t stage_u, int key0, bool valid, int tid) {
    if (valid) {
        #pragma unroll
        for (int c = tid; c < 4096; c += 256) {
            int half = c >> 11, cc = c & 2047;
            int row = cc >> 4, ch = cc & 15;
            uint32_t off = (uint32_t)(row * 256 + (((ch ^ (row & 7))) << 4));
            const __nv_bfloat16* src =
                (half ? g_kl : g_kh) + (size_t)(key0 + row) * DIM + ch * 8;
            cp16(stage_u + half * 32768 + off, src);
        }
    }
    CP_COMMIT();
}

// ---------------- main fused kernel ----------------
__global__ void __launch_bounds__(256, 1)
sim_topk(int N, int Ntiles) {
    extern __shared__ __align__(16) char sm[];
    uint32_t smb = smem_u32(sm);
    uint32_t stage_u = (smb + 1023u) & ~1023u;

    int tid = threadIdx.x;
    int wid = tid >> 5;
    int lane = tid & 31;
    int qbase = blockIdx.x * 128;
    int chunk = blockIdx.y;

    int TPC = (Ntiles + NCHUNKS - 1) / NCHUNKS;
    int t0 = chunk * TPC;
    int T = min(TPC, Ntiles - t0); if (T < 0) T = 0;

    // kick off the first two key-tile loads
    load_ktile(stage_u,         (t0 + 0) * 128, 0 < T, tid);
    load_ktile(stage_u + 65536, (t0 + 1) * 128, 1 < T, tid);

    // ---- preload A fragments (this warp's 16 query rows), hi and lo
    int qr = qbase + wid * 16 + (lane >> 2);
    const __nv_bfloat16* qh = g_qh + (size_t)qr * DIM;
    const __nv_bfloat16* ql = g_ql + (size_t)qr * DIM;
    uint32_t ah[8][4], al[8][4];
    #pragma unroll
    for (int kc = 0; kc < 8; ++kc) {
        int c = kc * 16 + (lane & 3) * 2;
        ah[kc][0] = *(const uint32_t*)(qh + c);
        ah[kc][1] = *(const uint32_t*)(qh + 8 * DIM + c);
        ah[kc][2] = *(const uint32_t*)(qh + c + 8);
        ah[kc][3] = *(const uint32_t*)(qh + 8 * DIM + c + 8);
        al[kc][0] = *(const uint32_t*)(ql + c);
        al[kc][1] = *(const uint32_t*)(ql + 8 * DIM + c);
        al[kc][2] = *(const uint32_t*)(ql + c + 8);
        al[kc][3] = *(const uint32_t*)(ql + 8 * DIM + c + 8);
    }

    int exq0 = g_excl[qbase + wid * 16 + (lane >> 2)];
    int exq1 = g_excl[qbase + wid * 16 + (lane >> 2) + 8];

    float tv0[5], tv1[5]; int ti0[5], ti1[5];
    #pragma unroll
    for (int r = 0; r < 5; ++r) {
        tv0[r] = -INFINITY; ti0[r] = -1;
        tv1[r] = -INFINITY; ti1[r] = -1;
    }

    // per-lane ldmatrix address components
    int r_   = lane & 7;
    int cbit = (lane >> 3) & 1;
    int kb256 = ((lane >> 4) * 8 + r_) * 256;   // key-within-pair * 256

    for (int t = 0; t < T; ++t) {
        CP_WAIT(1);
        __syncthreads();
        uint32_t st = stage_u + (t & 1) * 65536;

        float acc[16][4];
        #pragma unroll
        for (int nb = 0; nb < 16; ++nb)
            #pragma unroll
            for (int j = 0; j < 4; ++j) acc[nb][j] = 0.f;

        #pragma unroll
        for (int kc = 0; kc < 8; ++kc) {
            uint32_t ch = (uint32_t)(((kc * 2 + cbit) ^ r_) << 4);
            uint32_t base_h = st + kb256 + ch;
            uint32_t base_l = base_h + 32768;
            #pragma unroll
            for (int nbp = 0; nbp < 8; ++nbp) {
                uint32_t bh0, bh1, bh2, bh3, bl0, bl1, bl2, bl3;
                LDSM4(bh0, bh1, bh2, bh3, base_h + nbp * 4096);
                LDSM4(bl0, bl1, bl2, bl3, base_l + nbp * 4096);
                MMA16816(acc[2 * nbp],     ah[kc], bh0, bh1);
                MMA16816(acc[2 * nbp + 1], ah[kc], bh2, bh3);
                MMA16816(acc[2 * nbp],     al[kc], bh0, bh1);
                MMA16816(acc[2 * nbp + 1], al[kc], bh2, bh3);
                MMA16816(acc[2 * nbp],     ah[kc], bl0, bl1);
                MMA16816(acc[2 * nbp + 1], ah[kc], bl2, bl3);
            }
        }
        __syncthreads();   // everyone done reading this stage

        // prefetch tile t+2 into the stage just consumed
        load_ktile(stage_u + (t & 1) * 65536, (t0 + t + 2) * 128, (t + 2) < T, tid);

        // ---- register-resident top-5 scan
        int c0 = (t0 + t) * 128 + (lane & 3) * 2;
        #pragma unroll
        for (int nb = 0; nb < 16; ++nb) {
            int kg = c0 + nb * 8;
            float s0 = acc[nb][0], s1 = acc[nb][1];
            float s2 = acc[nb][2], s3 = acc[nb][3];
            if (s0 > tv0[4] && kg < N     && kg != exq0)     t5_ins(tv0, ti0, s0, kg);
            if (s1 > tv0[4] && kg + 1 < N && kg + 1 != exq0) t5_ins(tv0, ti0, s1, kg + 1);
            if (s2 > tv1[4] && kg < N     && kg != exq1)     t5_ins(tv1, ti1, s2, kg);
            if (s3 > tv1[4] && kg + 1 < N && kg + 1 != exq1) t5_ins(tv1, ti1, s3, kg + 1);
        }
    }

    CP_WAIT(0);

    // merge across the 4 lanes that share each query row
    t5_merge_xor(tv0, ti0, 1); t5_merge_xor(tv0, ti0, 2);
    t5_merge_xor(tv1, ti1, 1); t5_merge_xor(tv1, ti1, 2);

    if ((lane & 3) == 0) {
        int row0 = wid * 16 + (lane >> 2);
        size_t b0 = ((size_t)(blockIdx.x * NCHUNKS + chunk) * 128 + row0) * TOPK;
        size_t b1 = ((size_t)(blockIdx.x * NCHUNKS + chunk) * 128 + row0 + 8) * TOPK;
        #pragma unroll
        for (int r = 0; r < 5; ++r) {
            g_pval[b0 + r] = tv0[r]; g_pidx[b0 + r] = ti0[r];
            g_pval[b1 + r] = tv1[r]; g_pidx[b1 + r] = ti1[r];
        }
    }
}

// ---------------- merge partials, softmax, gather, normalize ----------------
__global__ void merge_out(const float* __restrict__ mem, float* __restrict__ out,
                          int N, int B) {
    int q = (blockIdx.x * blockDim.x + threadIdx.x) >> 5;
    int lane = threadIdx.x & 31;
    if (q >= B) return;
    int qtile = q >> 7, ql = q & 127;

    const int NCAND = NCHUNKS * TOPK;   // 90
    float cv[3]; int ci[3];
    #pragma unroll
    for (int s = 0; s < 3; ++s) {
        int cidx = lane + 32 * s;
        if (cidx < NCAND) {
            int c = cidx / TOPK, r = cidx % TOPK;
            size_t base = ((size_t)(qtile * NCHUNKS + c) * 128 + ql) * TOPK + r;
            cv[s] = g_pval[base]; ci[s] = g_pidx[base];
        } else { cv[s] = -INFINITY; ci[s] = 0x7fffffff; }
    }

    float tv[TOPK]; int ti[TOPK];
    #pragma unroll
    for (int r5 = 0; r5 < TOPK; ++r5) {
        float bv = cv[0]; int bi = ci[0];
        #pragma unroll
        for (int s = 1; s < 3; ++s)
            if (cv[s] > bv || (cv[s] == bv && ci[s] < bi)) { bv = cv[s]; bi = ci[s]; }
        float rv = bv; int ri = bi;
        #pragma unroll
        for (int o = 16; o; o >>= 1) {
            float ov = __shfl_xor_sync(0xffffffffu, rv, o);
            int   oi = __shfl_xor_sync(0xffffffffu, ri, o);
            if (ov > rv || (ov == rv && oi < ri)) { rv = ov; ri = oi; }
        }
        tv[r5] = rv; ti[r5] = ri;
        #pragma unroll
        for (int s = 0; s < 3; ++s) if (ci[s] == ri) cv[s] = -INFINITY;
    }

    float e[TOPK], ssum = 0.f;
    #pragma unroll
    for (int k = 0; k < TOPK; ++k) { e[k] = expf((tv[k] - tv[0]) * INV_T); ssum += e[k]; }
    float w[TOPK];
    #pragma unroll
    for (int k = 0; k < TOPK; ++k) w[k] = e[k] / ssum;

    int d0 = lane * 4;
    float4 a = make_float4(0.f, 0.f, 0.f, 0.f);
    #pragma unroll
    for (int k = 0; k < TOPK; ++k) {
        float4 m4 = *(const float4*)(mem + (size_t)ti[k] * DIM + d0);
        a.x += w[k] * m4.x; a.y += w[k] * m4.y; a.z += w[k] * m4.z; a.w += w[k] * m4.w;
    }
    float ss = a.x * a.x + a.y * a.y + a.z * a.z + a.w * a.w;
    #pragma unroll
    for (int o = 16; o; o >>= 1) ss += __shfl_xor_sync(0xffffffffu, ss, o);
    float sc = 1.0f / fmaxf(sqrtf(ss), 1e-12f);
    float4 r4 = make_float4(a.x * sc, a.y * sc, a.z * sc, a.w * sc);
    *(float4*)(out + (size_t)q * DIM + d0) = r4;

    if (lane == 0) {
        out[(size_t)B * DIM + q] = 1.0f - tv[0];
        #pragma unroll
        for (int k = 0; k < TOPK; ++k)
            out[(size_t)B * DIM + B + (size_t)q * TOPK + k] = w[k];
    }
}

// ---------------- launch ----------------
extern "C" void kernel_launch(void* const* d_in, const int* in_sizes, int n_in,
                              void* d_out, int out_size) {
    const float* query  = (const float*)d_in[0];
    const float* memory = (const float*)d_in[1];
    const void*  excl   = d_in[3];
    int B = in_sizes[0] / DIM;              // 1024
    int N = in_sizes[1] / DIM;              // 200000
    int Ntiles = (N + 127) / 128;           // 1563
    int NPAD = Ntiles * 128;
    float* out = (float*)d_out;

    prep_q<<<(B * 32 + 255) / 256, 256>>>(query, B);
    decode_exclude<<<1, 1024>>>(excl, B);
    split_mem<<<2048, 256>>>(memory, N, NPAD);

    const int SMEM = 2 * 65536 + 1024;      // 132,096 B
    cudaFuncSetAttribute(sim_topk, cudaFuncAttributeMaxDynamicSharedMemorySize, SMEM);
    sim_topk<<<dim3(B / 128, NCHUNKS), 256, SMEM>>>(N, Ntiles);

    merge_out<<<(B * 32 + 255) / 256, 256>>>(memory, out, N, B);
}

// round 4
// speedup vs baseline: 2.8371x; 1.1901x over previous
#include <cuda_runtime.h>
#include <cuda_bf16.h>
#include <math.h>
#include <stdint.h>

// ---------------- problem constants ----------------
#define MAXB     1024
#define DIM      128
#define NCHUNKS  18
#define TOPK     5
#define INV_T    10.0f
#define NPADMAX  (1564 * 128)

// ---------------- device scratch ----------------
__device__ int   g_excl[MAXB];
__device__ float g_pval[8 * NCHUNKS * 2 * 128 * TOPK];
__device__ int   g_pidx[8 * NCHUNKS * 2 * 128 * TOPK];
__device__ __nv_bfloat16 g_qh[MAXB * DIM];
__device__ __nv_bfloat16 g_ql[MAXB * DIM];
__device__ __nv_bfloat16 g_kh[(size_t)NPADMAX * DIM];   // 51.2 MB
__device__ __nv_bfloat16 g_kl[(size_t)NPADMAX * DIM];   // 51.2 MB

// ---------------- PTX helpers ----------------
__device__ __forceinline__ uint32_t smem_u32(const void* p) {
    uint32_t a;
    asm("{ .reg .u64 t; cvta.to.shared.u64 t, %1; cvt.u32.u64 %0, t; }" : "=r"(a) : "l"(p));
    return a;
}
__device__ __forceinline__ void cp16(uint32_t s, const void* g) {
    asm volatile("cp.async.cg.shared.global [%0], [%1], 16;" :: "r"(s), "l"(g));
}
#define CP_COMMIT()  asm volatile("cp.async.commit_group;")
#define CP_WAIT(n)   asm volatile("cp.async.wait_group %0;" :: "n"(n))

#define LDSM4(r0, r1, r2, r3, addr)                                         \
    asm volatile("ldmatrix.sync.aligned.m8n8.x4.shared.b16 {%0,%1,%2,%3}, [%4];" \
                 : "=r"(r0), "=r"(r1), "=r"(r2), "=r"(r3) : "r"(addr))

#define MMA16816(c, a, b0, b1)                                              \
    asm volatile("mma.sync.aligned.m16n8k16.row.col.f32.bf16.bf16.f32 "     \
                 "{%0,%1,%2,%3},{%4,%5,%6,%7},{%8,%9},{%0,%1,%2,%3};"       \
                 : "+f"((c)[0]), "+f"((c)[1]), "+f"((c)[2]), "+f"((c)[3])   \
                 : "r"((a)[0]), "r"((a)[1]), "r"((a)[2]), "r"((a)[3]),      \
                   "r"(b0), "r"(b1))

// ---------------- top-5 helpers (register resident) ----------------
__device__ __forceinline__ void t5_ins(float (&tv)[5], int (&ti)[5], float s, int idx) {
    tv[4] = s; ti[4] = idx;
    #pragma unroll
    for (int p = 4; p > 0; --p) {
        if (tv[p] > tv[p - 1]) {
            float fv = tv[p]; tv[p] = tv[p - 1]; tv[p - 1] = fv;
            int fi = ti[p]; ti[p] = ti[p - 1]; ti[p - 1] = fi;
        }
    }
}
__device__ __forceinline__ void t5_merge_xor(float (&tv)[5], int (&ti)[5], int off) {
    float pv[5]; int pi[5];
    #pragma unroll
    for (int r = 0; r < 5; ++r) {
        pv[r] = __shfl_xor_sync(0xffffffffu, tv[r], off);
        pi[r] = __shfl_xor_sync(0xffffffffu, ti[r], off);
    }
    #pragma unroll
    for (int r = 0; r < 5; ++r)
        if (pv[r] > tv[4]) t5_ins(tv, ti, pv[r], pi[r]);
}

// ---------------- kernel: normalize queries + bf16 hi/lo split --------------
__global__ void prep_q(const float* __restrict__ q, int B) {
    int w = (blockIdx.x * blockDim.x + threadIdx.x) >> 5;
    int lane = threadIdx.x & 31;
    if (w >= B) return;
    float4 v = *(const float4*)(q + (size_t)w * DIM + lane * 4);
    float ss = v.x * v.x + v.y * v.y + v.z * v.z + v.w * v.w;
    #pragma unroll
    for (int o = 16; o; o >>= 1) ss += __shfl_xor_sync(0xffffffffu, ss, o);
    float sc = 1.0f / fmaxf(sqrtf(ss), 1e-12f);
    float e[4] = { v.x * sc, v.y * sc, v.z * sc, v.w * sc };
    __nv_bfloat162 h0 = __floats2bfloat162_rn(e[0], e[1]);
    __nv_bfloat162 h1 = __floats2bfloat162_rn(e[2], e[3]);
    __nv_bfloat162 l0 = __floats2bfloat162_rn(e[0] - __low2float(h0), e[1] - __high2float(h0));
    __nv_bfloat162 l1 = __floats2bfloat162_rn(e[2] - __low2float(h1), e[3] - __high2float(h1));
    size_t off = (size_t)w * DIM + lane * 4;
    *(uint2*)(g_qh + off) = make_uint2(*(uint32_t*)&h0, *(uint32_t*)&h1);
    *(uint2*)(g_ql + off) = make_uint2(*(uint32_t*)&l0, *(uint32_t*)&l1);
}

// ---------------- kernel: decode exclude (int32/int64 sniff) ----------------
__global__ void decode_exclude(const void* __restrict__ ex, int B) {
    __shared__ int nz;
    int t = threadIdx.x;
    if (t == 0) nz = 0;
    __syncthreads();
    const int* e32 = (const int*)ex;
    if (t < B / 2) { if (e32[2 * t + 1] != 0) atomicAdd(&nz, 1); }
    __syncthreads();
    bool is64 = (nz == 0);
    if (t < B) {
        long long v = is64 ? ((const long long*)ex)[t] : (long long)e32[t];
        g_excl[t] = (int)v;
    }
}

// ---------------- kernel: fp32 memory -> bf16 hi/lo split ----------------
__global__ void split_mem(const float* __restrict__ mem, int N, int NPAD) {
    int total4 = NPAD * (DIM / 4);
    for (int i = blockIdx.x * blockDim.x + threadIdx.x; i < total4;
         i += gridDim.x * blockDim.x) {
        int row = i >> 5;
        float4 v = make_float4(0.f, 0.f, 0.f, 0.f);
        if (row < N) v = ((const float4*)mem)[i];
        __nv_bfloat162 h0 = __floats2bfloat162_rn(v.x, v.y);
        __nv_bfloat162 h1 = __floats2bfloat162_rn(v.z, v.w);
        __nv_bfloat162 l0 = __floats2bfloat162_rn(v.x - __low2float(h0), v.y - __high2float(h0));
        __nv_bfloat162 l1 = __floats2bfloat162_rn(v.z - __low2float(h1), v.w - __high2float(h1));
        ((uint2*)g_kh)[i] = make_uint2(*(uint32_t*)&h0, *(uint32_t*)&h1);
        ((uint2*)g_kl)[i] = make_uint2(*(uint32_t*)&l0, *(uint32_t*)&l1);
    }
}

// ---------------- key tile loader (XOR-swizzled rows for ldmatrix) ----------
// stage layout: [kh: 128 rows x 256B][kl: same]. row r, 16B chunk c (0..15):
// off = r*256 + ((c ^ (r&7)) << 4)
__device__ __forceinline__ void load_ktile(uint32_t stage_u, int key0, bool valid,
                                           int tid, int nthreads) {
    if (valid) {
        #pragma unroll
        for (int c = tid; c < 4096; c += 512) {
            int half = c >> 11, cc = c & 2047;
            int row = cc >> 4, ch = cc & 15;
            uint32_t off = (uint32_t)(row * 256 + (((ch ^ (row & 7))) << 4));
            const __nv_bfloat16* src =
                (half ? g_kl : g_kh) + (size_t)(key0 + row) * DIM + ch * 8;
            cp16(stage_u + half * 32768 + off, src);
        }
    }
    CP_COMMIT();
}

// ---------------- main fused kernel ----------------
__global__ void __launch_bounds__(512, 1)
sim_topk(int N, int Ntiles) {
    extern __shared__ __align__(16) char sm[];
    uint32_t smb = smem_u32(sm);
    uint32_t stage_u = (smb + 1023u) & ~1023u;

    int tid = threadIdx.x;
    int wid = tid >> 5;
    int lane = tid & 31;
    int wq = wid & 7;            // query-row group
    int khalf = wid >> 3;        // key half: 0 -> keys 0-63, 1 -> keys 64-127
    int qbase = blockIdx.x * 128;
    int chunk = blockIdx.y;

    int TPC = (Ntiles + NCHUNKS - 1) / NCHUNKS;
    int t0 = chunk * TPC;
    int T = min(TPC, Ntiles - t0); if (T < 0) T = 0;

    // prologue: stages 0 and 1
    load_ktile(stage_u,         (t0 + 0) * 128, 0 < T, tid, 512);
    load_ktile(stage_u + 65536, (t0 + 1) * 128, 1 < T, tid, 512);

    // ---- preload A fragments (this warp's 16 query rows), hi and lo
    int qr = qbase + wq * 16 + (lane >> 2);
    const __nv_bfloat16* qhp = g_qh + (size_t)qr * DIM;
    const __nv_bfloat16* qlp = g_ql + (size_t)qr * DIM;
    uint32_t ah[8][4], al[8][4];
    #pragma unroll
    for (int kc = 0; kc < 8; ++kc) {
        int c = kc * 16 + (lane & 3) * 2;
        ah[kc][0] = *(const uint32_t*)(qhp + c);
        ah[kc][1] = *(const uint32_t*)(qhp + 8 * DIM + c);
        ah[kc][2] = *(const uint32_t*)(qhp + c + 8);
        ah[kc][3] = *(const uint32_t*)(qhp + 8 * DIM + c + 8);
        al[kc][0] = *(const uint32_t*)(qlp + c);
        al[kc][1] = *(const uint32_t*)(qlp + 8 * DIM + c);
        al[kc][2] = *(const uint32_t*)(qlp + c + 8);
        al[kc][3] = *(const uint32_t*)(qlp + 8 * DIM + c + 8);
    }

    int exq0 = g_excl[qbase + wq * 16 + (lane >> 2)];
    int exq1 = g_excl[qbase + wq * 16 + (lane >> 2) + 8];

    float tv0[5], tv1[5]; int ti0[5], ti1[5];
    #pragma unroll
    for (int r = 0; r < 5; ++r) {
        tv0[r] = -INFINITY; ti0[r] = -1;
        tv1[r] = -INFINITY; ti1[r] = -1;
    }

    // per-lane ldmatrix address components (within this warp's 64-key half)
    int r_   = lane & 7;
    int cbit = (lane >> 3) & 1;
    int kb256 = (khalf << 14) + ((lane >> 4) * 8 + r_) * 256;

    for (int t = 0; t < T; ++t) {
        CP_WAIT(1);
        __syncthreads();

        // prefetch tile t+2 into stage (t+2)%3 (retired at iter t-1; barrier-safe)
        load_ktile(stage_u + ((t + 2) % 3) * 65536, (t0 + t + 2) * 128,
                   (t + 2) < T, tid, 512);

        uint32_t st = stage_u + (t % 3) * 65536;

        float acc[8][4];
        #pragma unroll
        for (int nb = 0; nb < 8; ++nb)
            #pragma unroll
            for (int j = 0; j < 4; ++j) acc[nb][j] = 0.f;

        #pragma unroll
        for (int kc = 0; kc < 8; ++kc) {
            uint32_t ch = (uint32_t)(((kc * 2 + cbit) ^ r_) << 4);
            uint32_t base_h = st + kb256 + ch;
            uint32_t base_l = base_h + 32768;
            #pragma unroll
            for (int nbp = 0; nbp < 4; ++nbp) {
                uint32_t bh0, bh1, bh2, bh3, bl0, bl1, bl2, bl3;
                LDSM4(bh0, bh1, bh2, bh3, base_h + nbp * 4096);
                LDSM4(bl0, bl1, bl2, bl3, base_l + nbp * 4096);
                MMA16816(acc[2 * nbp],     ah[kc], bh0, bh1);
                MMA16816(acc[2 * nbp + 1], ah[kc], bh2, bh3);
                MMA16816(acc[2 * nbp],     al[kc], bh0, bh1);
                MMA16816(acc[2 * nbp + 1], al[kc], bh2, bh3);
                MMA16816(acc[2 * nbp],     ah[kc], bl0, bl1);
                MMA16816(acc[2 * nbp + 1], ah[kc], bl2, bl3);
            }
        }

        // ---- register-resident top-5 scan (this warp's 64 keys)
        int c0 = (t0 + t) * 128 + khalf * 64 + (lane & 3) * 2;
        #pragma unroll
        for (int nb = 0; nb < 8; ++nb) {
            int kg = c0 + nb * 8;
            float s0 = acc[nb][0], s1 = acc[nb][1];
            float s2 = acc[nb][2], s3 = acc[nb][3];
            if (s0 > tv0[4] && kg < N     && kg != exq0)     t5_ins(tv0, ti0, s0, kg);
            if (s1 > tv0[4] && kg + 1 < N && kg + 1 != exq0) t5_ins(tv0, ti0, s1, kg + 1);
            if (s2 > tv1[4] && kg < N     && kg != exq1)     t5_ins(tv1, ti1, s2, kg);
            if (s3 > tv1[4] && kg + 1 < N && kg + 1 != exq1) t5_ins(tv1, ti1, s3, kg + 1);
        }
    }

    CP_WAIT(0);

    // merge across the 4 lanes that share each query row
    t5_merge_xor(tv0, ti0, 1); t5_merge_xor(tv0, ti0, 2);
    t5_merge_xor(tv1, ti1, 1); t5_merge_xor(tv1, ti1, 2);

    if ((lane & 3) == 0) {
        int row0 = wq * 16 + (lane >> 2);
        size_t slot = (size_t)((blockIdx.x * NCHUNKS + chunk) * 2 + khalf) * 128;
        size_t b0 = (slot + row0) * TOPK;
        size_t b1 = (slot + row0 + 8) * TOPK;
        #pragma unroll
        for (int r = 0; r < 5; ++r) {
            g_pval[b0 + r] = tv0[r]; g_pidx[b0 + r] = ti0[r];
            g_pval[b1 + r] = tv1[r]; g_pidx[b1 + r] = ti1[r];
        }
    }
}

// ---------------- merge partials, softmax, gather, normalize ----------------
#define NSLOTS (NCHUNKS * 2)     // 36 partial slots per q-tile
__global__ void merge_out(const float* __restrict__ mem, float* __restrict__ out,
                          int N, int B) {
    int q = (blockIdx.x * blockDim.x + threadIdx.x) >> 5;
    int lane = threadIdx.x & 31;
    if (q >= B) return;
    int qtile = q >> 7, ql = q & 127;

    const int NCAND = NSLOTS * TOPK;   // 180
    float cv[6]; int ci[6];
    #pragma unroll
    for (int s = 0; s < 6; ++s) {
        int cidx = lane + 32 * s;
        if (cidx < NCAND) {
            int c = cidx / TOPK, r = cidx % TOPK;
            size_t base = ((size_t)(qtile * NSLOTS + c) * 128 + ql) * TOPK + r;
            cv[s] = g_pval[base]; ci[s] = g_pidx[base];
        } else { cv[s] = -INFINITY; ci[s] = 0x7fffffff; }
    }

    float tv[TOPK]; int ti[TOPK];
    #pragma unroll
    for (int r5 = 0; r5 < TOPK; ++r5) {
        float bv = cv[0]; int bi = ci[0];
        #pragma unroll
        for (int s = 1; s < 6; ++s)
            if (cv[s] > bv || (cv[s] == bv && ci[s] < bi)) { bv = cv[s]; bi = ci[s]; }
        float rv = bv; int ri = bi;
        #pragma unroll
        for (int o = 16; o; o >>= 1) {
            float ov = __shfl_xor_sync(0xffffffffu, rv, o);
            int   oi = __shfl_xor_sync(0xffffffffu, ri, o);
            if (ov > rv || (ov == rv && oi < ri)) { rv = ov; ri = oi; }
        }
        tv[r5] = rv; ti[r5] = ri;
        #pragma unroll
        for (int s = 0; s < 6; ++s) if (ci[s] == ri) cv[s] = -INFINITY;
    }

    float e[TOPK], ssum = 0.f;
    #pragma unroll
    for (int k = 0; k < TOPK; ++k) { e[k] = expf((tv[k] - tv[0]) * INV_T); ssum += e[k]; }
    float w[TOPK];
    #pragma unroll
    for (int k = 0; k < TOPK; ++k) w[k] = e[k] / ssum;

    int d0 = lane * 4;
    float4 a = make_float4(0.f, 0.f, 0.f, 0.f);
    #pragma unroll
    for (int k = 0; k < TOPK; ++k) {
        float4 m4 = *(const float4*)(mem + (size_t)ti[k] * DIM + d0);
        a.x += w[k] * m4.x; a.y += w[k] * m4.y; a.z += w[k] * m4.z; a.w += w[k] * m4.w;
    }
    float ss = a.x * a.x + a.y * a.y + a.z * a.z + a.w * a.w;
    #pragma unroll
    for (int o = 16; o; o >>= 1) ss += __shfl_xor_sync(0xffffffffu, ss, o);
    float sc = 1.0f / fmaxf(sqrtf(ss), 1e-12f);
    float4 r4 = make_float4(a.x * sc, a.y * sc, a.z * sc, a.w * sc);
    *(float4*)(out + (size_t)q * DIM + d0) = r4;

    if (lane == 0) {
        out[(size_t)B * DIM + q] = 1.0f - tv[0];
        #pragma unroll
        for (int k = 0; k < TOPK; ++k)
            out[(size_t)B * DIM + B + (size_t)q * TOPK + k] = w[k];
    }
}

// ---------------- launch ----------------
extern "C" void kernel_launch(void* const* d_in, const int* in_sizes, int n_in,
                              void* d_out, int out_size) {
    const float* query  = (const float*)d_in[0];
    const float* memory = (const float*)d_in[1];
    const void*  excl   = d_in[3];
    int B = in_sizes[0] / DIM;              // 1024
    int N = in_sizes[1] / DIM;              // 200000
    int Ntiles = (N + 127) / 128;           // 1563
    int NPAD = Ntiles * 128;
    float* out = (float*)d_out;

    prep_q<<<(B * 32 + 255) / 256, 256>>>(query, B);
    decode_exclude<<<1, 1024>>>(excl, B);
    split_mem<<<2048, 256>>>(memory, N, NPAD);

    const int SMEM = 3 * 65536 + 1024;      // 197,632 B
    cudaFuncSetAttribute(sim_topk, cudaFuncAttributeMaxDynamicSharedMemorySize, SMEM);
    sim_topk<<<dim3(B / 128, NCHUNKS), 512, SMEM>>>(N, Ntiles);

    merge_out<<<(B * 32 + 255) / 256, 256>>>(memory, out, N, B);
}

// round 5
// speedup vs baseline: 3.5579x; 1.2541x over previous
#include <cuda_runtime.h>
#include <cuda_bf16.h>
#include <math.h>
#include <stdint.h>

// ---------------- problem constants ----------------
#define MAXB     1024
#define DIM      128
#define NCHUNKS  18
#define NSLOTS   (NCHUNKS * 2)     // per-chunk key-halves
#define K8       8                 // per-slot candidate depth
#define TOPK     5
#define RESC     10                // rescored candidates per query
#define INV_T    10.0f
#define NPADMAX  (1564 * 128)

// ---------------- device scratch ----------------
__device__ int   g_excl[MAXB];
__device__ float g_qn[MAXB * DIM];                       // normalized queries fp32
__device__ float g_pval[8 * NSLOTS * 128 * K8];
__device__ int   g_pidx[8 * NSLOTS * 128 * K8];
__device__ __nv_bfloat16 g_qh[MAXB * DIM];
__device__ __nv_bfloat16 g_kh[(size_t)NPADMAX * DIM];    // 51.2 MB

// ---------------- PTX helpers ----------------
__device__ __forceinline__ uint32_t smem_u32(const void* p) {
    uint32_t a;
    asm("{ .reg .u64 t; cvta.to.shared.u64 t, %1; cvt.u32.u64 %0, t; }" : "=r"(a) : "l"(p));
    return a;
}
__device__ __forceinline__ void cp16(uint32_t s, const void* g) {
    asm volatile("cp.async.cg.shared.global [%0], [%1], 16;" :: "r"(s), "l"(g));
}
#define CP_COMMIT()  asm volatile("cp.async.commit_group;")
#define CP_WAIT(n)   asm volatile("cp.async.wait_group %0;" :: "n"(n))

#define LDSM4(r0, r1, r2, r3, addr)                                         \
    asm volatile("ldmatrix.sync.aligned.m8n8.x4.shared.b16 {%0,%1,%2,%3}, [%4];" \
                 : "=r"(r0), "=r"(r1), "=r"(r2), "=r"(r3) : "r"(addr))

#define MMA16816(c, a, b0, b1)                                              \
    asm volatile("mma.sync.aligned.m16n8k16.row.col.f32.bf16.bf16.f32 "     \
                 "{%0,%1,%2,%3},{%4,%5,%6,%7},{%8,%9},{%0,%1,%2,%3};"       \
                 : "+f"((c)[0]), "+f"((c)[1]), "+f"((c)[2]), "+f"((c)[3])   \
                 : "r"((a)[0]), "r"((a)[1]), "r"((a)[2]), "r"((a)[3]),      \
                   "r"(b0), "r"(b1))

// ---------------- top-8 helpers (register resident) ----------------
__device__ __forceinline__ void t8_ins(float (&tv)[K8], int (&ti)[K8], float s, int idx) {
    tv[K8 - 1] = s; ti[K8 - 1] = idx;
    #pragma unroll
    for (int p = K8 - 1; p > 0; --p) {
        if (tv[p] > tv[p - 1]) {
            float fv = tv[p]; tv[p] = tv[p - 1]; tv[p - 1] = fv;
            int fi = ti[p]; ti[p] = ti[p - 1]; ti[p - 1] = fi;
        }
    }
}
__device__ __forceinline__ void t8_merge_xor(float (&tv)[K8], int (&ti)[K8], int off) {
    float pv[K8]; int pi[K8];
    #pragma unroll
    for (int r = 0; r < K8; ++r) {
        pv[r] = __shfl_xor_sync(0xffffffffu, tv[r], off);
        pi[r] = __shfl_xor_sync(0xffffffffu, ti[r], off);
    }
    #pragma unroll
    for (int r = 0; r < K8; ++r)
        if (pv[r] > tv[K8 - 1]) t8_ins(tv, ti, pv[r], pi[r]);
}

// ---------------- kernel: normalize queries (fp32 + bf16-hi) ----------------
__global__ void prep_q(const float* __restrict__ q, int B) {
    int w = (blockIdx.x * blockDim.x + threadIdx.x) >> 5;
    int lane = threadIdx.x & 31;
    if (w >= B) return;
    float4 v = *(const float4*)(q + (size_t)w * DIM + lane * 4);
    float ss = v.x * v.x + v.y * v.y + v.z * v.z + v.w * v.w;
    #pragma unroll
    for (int o = 16; o; o >>= 1) ss += __shfl_xor_sync(0xffffffffu, ss, o);
    float sc = 1.0f / fmaxf(sqrtf(ss), 1e-12f);
    float4 r = make_float4(v.x * sc, v.y * sc, v.z * sc, v.w * sc);
    size_t off = (size_t)w * DIM + lane * 4;
    *(float4*)(g_qn + off) = r;
    __nv_bfloat162 h0 = __floats2bfloat162_rn(r.x, r.y);
    __nv_bfloat162 h1 = __floats2bfloat162_rn(r.z, r.w);
    *(uint2*)(g_qh + off) = make_uint2(*(uint32_t*)&h0, *(uint32_t*)&h1);
}

// ---------------- kernel: decode exclude (int32/int64 sniff) ----------------
__global__ void decode_exclude(const void* __restrict__ ex, int B) {
    __shared__ int nz;
    int t = threadIdx.x;
    if (t == 0) nz = 0;
    __syncthreads();
    const int* e32 = (const int*)ex;
    if (t < B / 2) { if (e32[2 * t + 1] != 0) atomicAdd(&nz, 1); }
    __syncthreads();
    bool is64 = (nz == 0);
    if (t < B) {
        long long v = is64 ? ((const long long*)ex)[t] : (long long)e32[t];
        g_excl[t] = (int)v;
    }
}

// ---------------- kernel: fp32 memory -> bf16 hi ----------------
__global__ void split_mem(const float* __restrict__ mem, int N, int NPAD) {
    int total4 = NPAD * (DIM / 4);
    for (int i = blockIdx.x * blockDim.x + threadIdx.x; i < total4;
         i += gridDim.x * blockDim.x) {
        int row = i >> 5;
        float4 v = make_float4(0.f, 0.f, 0.f, 0.f);
        if (row < N) v = ((const float4*)mem)[i];
        __nv_bfloat162 h0 = __floats2bfloat162_rn(v.x, v.y);
        __nv_bfloat162 h1 = __floats2bfloat162_rn(v.z, v.w);
        ((uint2*)g_kh)[i] = make_uint2(*(uint32_t*)&h0, *(uint32_t*)&h1);
    }
}

// ---------------- key tile loader (XOR-swizzled rows for ldmatrix) ----------
// 128 rows x 256B. row r, 16B chunk c: off = r*256 + ((c ^ (r&7)) << 4)
__device__ __forceinline__ void load_ktile(uint32_t stage_u, int key0, bool valid, int tid) {
    if (valid) {
        #pragma unroll
        for (int c = tid; c < 2048; c += 512) {
            int row = c >> 4, ch = c & 15;
            uint32_t off = (uint32_t)(row * 256 + (((ch ^ (row & 7))) << 4));
            cp16(stage_u + off, g_kh + (size_t)(key0 + row) * DIM + ch * 8);
        }
    }
    CP_COMMIT();
}

// ---------------- main filter kernel: approx sims + streaming top-8 ---------
__global__ void __launch_bounds__(512, 1)
sim_topk(int N, int Ntiles) {
    extern __shared__ __align__(16) char sm[];
    uint32_t smb = smem_u32(sm);
    uint32_t stage_u = (smb + 1023u) & ~1023u;

    int tid = threadIdx.x;
    int wid = tid >> 5;
    int lane = tid & 31;
    int wq = wid & 7;            // query-row group
    int khalf = wid >> 3;        // key half
    int qbase = blockIdx.x * 128;
    int chunk = blockIdx.y;

    int TPC = (Ntiles + NCHUNKS - 1) / NCHUNKS;
    int t0 = chunk * TPC;
    int T = min(TPC, Ntiles - t0); if (T < 0) T = 0;

    load_ktile(stage_u,         (t0 + 0) * 128, 0 < T, tid);
    load_ktile(stage_u + 32768, (t0 + 1) * 128, 1 < T, tid);

    // preload A fragments (bf16-hi of this warp's 16 query rows)
    int qr = qbase + wq * 16 + (lane >> 2);
    const __nv_bfloat16* qhp = g_qh + (size_t)qr * DIM;
    uint32_t ah[8][4];
    #pragma unroll
    for (int kc = 0; kc < 8; ++kc) {
        int c = kc * 16 + (lane & 3) * 2;
        ah[kc][0] = *(const uint32_t*)(qhp + c);
        ah[kc][1] = *(const uint32_t*)(qhp + 8 * DIM + c);
        ah[kc][2] = *(const uint32_t*)(qhp + c + 8);
        ah[kc][3] = *(const uint32_t*)(qhp + 8 * DIM + c + 8);
    }

    int exq0 = g_excl[qbase + wq * 16 + (lane >> 2)];
    int exq1 = g_excl[qbase + wq * 16 + (lane >> 2) + 8];

    float tv0[K8], tv1[K8]; int ti0[K8], ti1[K8];
    #pragma unroll
    for (int r = 0; r < K8; ++r) {
        tv0[r] = -INFINITY; ti0[r] = -1;
        tv1[r] = -INFINITY; ti1[r] = -1;
    }

    int r_   = lane & 7;
    int cbit = (lane >> 3) & 1;
    int kb256 = (khalf << 14) + ((lane >> 4) * 8 + r_) * 256;

    for (int t = 0; t < T; ++t) {
        CP_WAIT(1);
        __syncthreads();

        load_ktile(stage_u + ((t + 2) % 3) * 32768, (t0 + t + 2) * 128,
                   (t + 2) < T, tid);

        uint32_t st = stage_u + (t % 3) * 32768;

        float acc[8][4];
        #pragma unroll
        for (int nb = 0; nb < 8; ++nb)
            #pragma unroll
            for (int j = 0; j < 4; ++j) acc[nb][j] = 0.f;

        #pragma unroll
        for (int kc = 0; kc < 8; ++kc) {
            uint32_t ch = (uint32_t)(((kc * 2 + cbit) ^ r_) << 4);
            uint32_t base_h = st + kb256 + ch;
            #pragma unroll
            for (int nbp = 0; nbp < 4; ++nbp) {
                uint32_t bh0, bh1, bh2, bh3;
                LDSM4(bh0, bh1, bh2, bh3, base_h + nbp * 4096);
                MMA16816(acc[2 * nbp],     ah[kc], bh0, bh1);
                MMA16816(acc[2 * nbp + 1], ah[kc], bh2, bh3);
            }
        }

        // streaming top-8 scan (this warp's 64 keys)
        int c0 = (t0 + t) * 128 + khalf * 64 + (lane & 3) * 2;
        #pragma unroll
        for (int nb = 0; nb < 8; ++nb) {
            int kg = c0 + nb * 8;
            float s0 = acc[nb][0], s1 = acc[nb][1];
            float s2 = acc[nb][2], s3 = acc[nb][3];
            if (s0 > tv0[K8-1] && kg < N     && kg != exq0)     t8_ins(tv0, ti0, s0, kg);
            if (s1 > tv0[K8-1] && kg + 1 < N && kg + 1 != exq0) t8_ins(tv0, ti0, s1, kg + 1);
            if (s2 > tv1[K8-1] && kg < N     && kg != exq1)     t8_ins(tv1, ti1, s2, kg);
            if (s3 > tv1[K8-1] && kg + 1 < N && kg + 1 != exq1) t8_ins(tv1, ti1, s3, kg + 1);
        }
    }

    CP_WAIT(0);

    // merge across the 4 lanes sharing each query row
    t8_merge_xor(tv0, ti0, 1); t8_merge_xor(tv0, ti0, 2);
    t8_merge_xor(tv1, ti1, 1); t8_merge_xor(tv1, ti1, 2);

    if ((lane & 3) == 0) {
        int row0 = wq * 16 + (lane >> 2);
        size_t slot = (size_t)((blockIdx.x * NCHUNKS + chunk) * 2 + khalf) * 128;
        size_t b0 = (slot + row0) * K8;
        size_t b1 = (slot + row0 + 8) * K8;
        #pragma unroll
        for (int r = 0; r < K8; ++r) {
            g_pval[b0 + r] = tv0[r]; g_pidx[b0 + r] = ti0[r];
            g_pval[b1 + r] = tv1[r]; g_pidx[b1 + r] = ti1[r];
        }
    }
}

// ---------------- merge + exact rescore + softmax/gather/normalize ----------
__global__ void merge_out(const float* __restrict__ mem, float* __restrict__ out,
                          int N, int B) {
    int q = (blockIdx.x * blockDim.x + threadIdx.x) >> 5;
    int lane = threadIdx.x & 31;
    if (q >= B) return;
    int qtile = q >> 7, ql = q & 127;

    // ---- phase 1: approx top-RESC of 288 candidates (9 per lane)
    float cv[9]; int ci[9];
    #pragma unroll
    for (int s = 0; s < 9; ++s) {
        int cidx = lane + 32 * s;                       // < 288 always
        int c = cidx / K8, r = cidx % K8;
        size_t base = ((size_t)(qtile * NSLOTS + c) * 128 + ql) * K8 + r;
        cv[s] = g_pval[base]; ci[s] = g_pidx[base];
    }

    int ridx[RESC];
    #pragma unroll
    for (int k = 0; k < RESC; ++k) {
        float bv = cv[0]; int bi = ci[0];
        #pragma unroll
        for (int s = 1; s < 9; ++s)
            if (cv[s] > bv || (cv[s] == bv && ci[s] < bi)) { bv = cv[s]; bi = ci[s]; }
        #pragma unroll
        for (int o = 16; o; o >>= 1) {
            float ov = __shfl_xor_sync(0xffffffffu, bv, o);
            int   oi = __shfl_xor_sync(0xffffffffu, bi, o);
            if (ov > bv || (ov == bv && oi < bi)) { bv = ov; bi = oi; }
        }
        ridx[k] = bi;
        #pragma unroll
        for (int s = 0; s < 9; ++s) if (ci[s] == bi) cv[s] = -INFINITY;
    }

    // ---- phase 2: exact fp32 rescore of the RESC survivors
    float4 qv = *(const float4*)(g_qn + (size_t)q * DIM + lane * 4);
    float rv[RESC];
    #pragma unroll
    for (int k = 0; k < RESC; ++k) {
        float4 m4 = *(const float4*)(mem + (size_t)ridx[k] * DIM + lane * 4);
        float d = qv.x * m4.x + qv.y * m4.y + qv.z * m4.z + qv.w * m4.w;
        #pragma unroll
        for (int o = 16; o; o >>= 1) d += __shfl_xor_sync(0xffffffffu, d, o);
        rv[k] = d;
    }

    // ---- phase 3: exact top-5 (lower index wins ties), all lanes redundant
    float tv[TOPK]; int ti[TOPK];
    int usedmask = 0;
    #pragma unroll
    for (int k = 0; k < TOPK; ++k) {
        float bv = -INFINITY; int bi = 0x7fffffff, bs = -1;
        #pragma unroll
        for (int r = 0; r < RESC; ++r)
            if (!((usedmask >> r) & 1) &&
                (rv[r] > bv || (rv[r] == bv && ridx[r] < bi))) {
                bv = rv[r]; bi = ridx[r]; bs = r;
            }
        usedmask |= 1 << bs;
        tv[k] = bv; ti[k] = bi;
    }

    // ---- softmax over exact top sims
    float e[TOPK], ssum = 0.f;
    #pragma unroll
    for (int k = 0; k < TOPK; ++k) { e[k] = expf((tv[k] - tv[0]) * INV_T); ssum += e[k]; }
    float w[TOPK];
    #pragma unroll
    for (int k = 0; k < TOPK; ++k) w[k] = e[k] / ssum;

    // ---- weighted gather + renormalize
    int d0 = lane * 4;
    float4 a = make_float4(0.f, 0.f, 0.f, 0.f);
    #pragma unroll
    for (int k = 0; k < TOPK; ++k) {
        float4 m4 = *(const float4*)(mem + (size_t)ti[k] * DIM + d0);
        a.x += w[k] * m4.x; a.y += w[k] * m4.y; a.z += w[k] * m4.z; a.w += w[k] * m4.w;
    }
    float ss = a.x * a.x + a.y * a.y + a.z * a.z + a.w * a.w;
    #pragma unroll
    for (int o = 16; o; o >>= 1) ss += __shfl_xor_sync(0xffffffffu, ss, o);
    float sc = 1.0f / fmaxf(sqrtf(ss), 1e-12f);
    float4 r4 = make_float4(a.x * sc, a.y * sc, a.z * sc, a.w * sc);
    *(float4*)(out + (size_t)q * DIM + d0) = r4;

    if (lane == 0) {
        out[(size_t)B * DIM + q] = 1.0f - tv[0];
        #pragma unroll
        for (int k = 0; k < TOPK; ++k)
            out[(size_t)B * DIM + B + (size_t)q * TOPK + k] = w[k];
    }
}

// ---------------- launch ----------------
extern "C" void kernel_launch(void* const* d_in, const int* in_sizes, int n_in,
                              void* d_out, int out_size) {
    const float* query  = (const float*)d_in[0];
    const float* memory = (const float*)d_in[1];
    const void*  excl   = d_in[3];
    int B = in_sizes[0] / DIM;              // 1024
    int N = in_sizes[1] / DIM;              // 200000
    int Ntiles = (N + 127) / 128;           // 1563
    int NPAD = Ntiles * 128;
    float* out = (float*)d_out;

    prep_q<<<(B * 32 + 255) / 256, 256>>>(query, B);
    decode_exclude<<<1, 1024>>>(excl, B);
    split_mem<<<2048, 256>>>(memory, N, NPAD);

    const int SMEM = 3 * 32768 + 1024;      // 99,328 B
    cudaFuncSetAttribute(sim_topk, cudaFuncAttributeMaxDynamicSharedMemorySize, SMEM);
    sim_topk<<<dim3(B / 128, NCHUNKS), 512, SMEM>>>(N, Ntiles);

    merge_out<<<(B * 32 + 255) / 256, 256>>>(memory, out, N, B);
}